// round 6
// baseline (speedup 1.0000x reference)
#include <cuda_runtime.h>
#include <cstdint>

// Problem constants
#define B_    2
#define NSEQ  2048
#define DIM_  1024
#define H_    16
#define HD_   64
#define SCALE_F 0.125f   // HD^-0.5

// Scratch (device globals: allocation-free contract)
__device__ __align__(16) float g_Q [B_*H_*NSEQ*HD_];   // [bh][n][d], pre-scaled
__device__ __align__(16) float g_K [B_*H_*NSEQ*HD_];   // [bh][n][d]
__device__ __align__(16) float g_V [B_*H_*NSEQ*HD_];   // [bh][n][d]
__device__ __align__(16) float g_AO[B_*NSEQ*DIM_];     // attention out [b*n][dim]

// ---------------------------------------------------------------------------
// bf16x2 split helpers: hi = top16(fp32), lo = bf16(x - hi). 3-mma split.
// ---------------------------------------------------------------------------
__device__ __forceinline__ uint32_t packhi2(float x, float y) {
    return __byte_perm(__float_as_uint(x), __float_as_uint(y), 0x7632);
}
__device__ __forceinline__ uint32_t packlo2(float x, float y) {
    float lx = x - __uint_as_float(__float_as_uint(x) & 0xffff0000u);
    float ly = y - __uint_as_float(__float_as_uint(y) & 0xffff0000u);
    return __byte_perm(__float_as_uint(lx), __float_as_uint(ly), 0x7632);
}
__device__ __forceinline__ void split4(float4 v, uint32_t* hi, uint32_t* lo) {
    hi[0] = packhi2(v.x, v.y); hi[1] = packhi2(v.z, v.w);
    lo[0] = packlo2(v.x, v.y); lo[1] = packlo2(v.z, v.w);
}
__device__ __forceinline__ uint32_t smem_u32(const void* p) {
    uint32_t a;
    asm("{ .reg .u64 t; cvta.to.shared.u64 t, %1; cvt.u32.u64 %0, t; }" : "=r"(a) : "l"(p));
    return a;
}
__device__ __forceinline__ void mma16(float* c, const uint32_t* a, const uint32_t* b) {
    asm("mma.sync.aligned.m16n8k16.row.col.f32.bf16.bf16.f32 "
        "{%0,%1,%2,%3}, {%4,%5,%6,%7}, {%8,%9}, {%0,%1,%2,%3};"
        : "+f"(c[0]), "+f"(c[1]), "+f"(c[2]), "+f"(c[3])
        : "r"(a[0]), "r"(a[1]), "r"(a[2]), "r"(a[3]), "r"(b[0]), "r"(b[1]));
}
__device__ __forceinline__ void ldmx4(uint32_t* r, uint32_t a) {
    asm volatile("ldmatrix.sync.aligned.m8n8.x4.shared.b16 {%0,%1,%2,%3}, [%4];"
        : "=r"(r[0]), "=r"(r[1]), "=r"(r[2]), "=r"(r[3]) : "r"(a));
}
__device__ __forceinline__ void ldmx4t(uint32_t* r, uint32_t a) {
    asm volatile("ldmatrix.sync.aligned.m8n8.x4.trans.shared.b16 {%0,%1,%2,%3}, [%4];"
        : "=r"(r[0]), "=r"(r[1]), "=r"(r[2]), "=r"(r[3]) : "r"(a));
}

// ---------------------------------------------------------------------------
// Split-bf16 GEMM: C[4096, Ncols] = A @ W^T + bias.  CTA 128x128, 8 warps
// (2x4, warp 64x32), BK=32, double-buffered smem, ldmatrix, 2 CTAs/SM.
// Smem word layout per buffer: [AHI][ALO][BHI][BLO], each [128][20].
// ---------------------------------------------------------------------------
#define GST 20
#define GARR (128*GST)        // 2560 words
#define GBUF (4*GARR)         // 10240 words per buffer
#define GEMM_SMEM (2*GBUF*4)  // 81920 B

template<int MODE>
__global__ __launch_bounds__(256, 2)
void tc_gemm(const float* __restrict__ Ain, const float* __restrict__ W,
             const float* __restrict__ bias, float* __restrict__ C)
{
    extern __shared__ __align__(16) uint32_t smu[];
    const uint32_t sb = smem_u32(smu);
    const float* A = (MODE == 1) ? (const float*)g_AO : Ain;

    const int tid = threadIdx.x;
    const int wid = tid >> 5, lane = tid & 31;
    const int g = lane >> 2, tg = lane & 3;
    const int wm = wid >> 2, wn = wid & 3;
    const int row0 = blockIdx.y * 128, col0 = blockIdx.x * 128;

    // ldmatrix per-lane address components (word units)
    const int rA = wm * 64 + (lane & 15);
    const int kA = (lane >> 4) * 4;
    const int rB = wn * 32 + (lane & 7) + ((lane >> 4) << 3);
    const int kB = ((lane >> 3) & 1) * 4;

    float c[4][4][4];
#pragma unroll
    for (int mt = 0; mt < 4; mt++)
#pragma unroll
        for (int nt = 0; nt < 4; nt++) {
            c[mt][nt][0] = 0.f; c[mt][nt][1] = 0.f; c[mt][nt][2] = 0.f; c[mt][nt][3] = 0.f;
        }

    const int lr = tid >> 1, lhalf = tid & 1;
    float4 a4[4], b4[4];
    auto ldg = [&](int ch) {
        const float* ap = A + (size_t)(row0 + lr) * DIM_ + ch * 32 + lhalf * 16;
        const float* bp = W + (size_t)(col0 + lr) * DIM_ + ch * 32 + lhalf * 16;
#pragma unroll
        for (int j = 0; j < 4; j++) {
            a4[j] = *(const float4*)(ap + 4 * j);
            b4[j] = *(const float4*)(bp + 4 * j);
        }
    };
    auto sts = [&](int buf) {
        const int bo = buf * GBUF;
#pragma unroll
        for (int j = 0; j < 4; j++) {
            uint32_t hi[2], lo[2];
            int k2 = lhalf * 8 + 2 * j;
            split4(a4[j], hi, lo);
            *(uint2*)&smu[bo + lr * GST + k2]            = make_uint2(hi[0], hi[1]);
            *(uint2*)&smu[bo + GARR + lr * GST + k2]     = make_uint2(lo[0], lo[1]);
            split4(b4[j], hi, lo);
            *(uint2*)&smu[bo + 2 * GARR + lr * GST + k2] = make_uint2(hi[0], hi[1]);
            *(uint2*)&smu[bo + 3 * GARR + lr * GST + k2] = make_uint2(lo[0], lo[1]);
        }
    };

    ldg(0); sts(0);
    __syncthreads();

    for (int ch = 0; ch < 32; ch++) {
        if (ch < 31) ldg(ch + 1);
        const uint32_t bo = sb + (uint32_t)(ch & 1) * (GBUF * 4);
#pragma unroll
        for (int ks = 0; ks < 2; ks++) {
            const int kb = ks * 8;
            uint32_t ah[4][4], al[4][4];
#pragma unroll
            for (int mt = 0; mt < 4; mt++) {
                ldmx4(ah[mt], bo + (uint32_t)((rA + mt * 16) * GST + kb + kA) * 4);
                ldmx4(al[mt], bo + (uint32_t)(GARR + (rA + mt * 16) * GST + kb + kA) * 4);
            }
            uint32_t bh[4][2], bl[4][2];
#pragma unroll
            for (int ntp = 0; ntp < 2; ntp++) {
                uint32_t t[4];
                ldmx4(t, bo + (uint32_t)(2 * GARR + (rB + ntp * 16) * GST + kb + kB) * 4);
                bh[2*ntp][0] = t[0]; bh[2*ntp][1] = t[1];
                bh[2*ntp+1][0] = t[2]; bh[2*ntp+1][1] = t[3];
                ldmx4(t, bo + (uint32_t)(3 * GARR + (rB + ntp * 16) * GST + kb + kB) * 4);
                bl[2*ntp][0] = t[0]; bl[2*ntp][1] = t[1];
                bl[2*ntp+1][0] = t[2]; bl[2*ntp+1][1] = t[3];
            }
            // 3 passes of 16 independent mmas: no same-accumulator adjacency
#pragma unroll
            for (int nt = 0; nt < 4; nt++)
#pragma unroll
                for (int mt = 0; mt < 4; mt++) mma16(c[mt][nt], ah[mt], bh[nt]);
#pragma unroll
            for (int nt = 0; nt < 4; nt++)
#pragma unroll
                for (int mt = 0; mt < 4; mt++) mma16(c[mt][nt], ah[mt], bl[nt]);
#pragma unroll
            for (int nt = 0; nt < 4; nt++)
#pragma unroll
                for (int mt = 0; mt < 4; mt++) mma16(c[mt][nt], al[mt], bh[nt]);
        }
        if (ch < 31) { sts((ch + 1) & 1); __syncthreads(); }
    }

    // Epilogue
#pragma unroll
    for (int mt = 0; mt < 4; mt++) {
#pragma unroll
        for (int half = 0; half < 2; half++) {
            int row = row0 + wm * 64 + mt * 16 + g + half * 8;
#pragma unroll
            for (int nt = 0; nt < 4; nt++) {
                int col = col0 + wn * 32 + nt * 8 + 2 * tg;
                float v0 = c[mt][nt][half * 2 + 0] + bias[col];
                float v1 = c[mt][nt][half * 2 + 1] + bias[col + 1];
                if (MODE == 1) {
                    *(float2*)&C[(size_t)row * DIM_ + col] = make_float2(v0, v1);
                } else {
                    int b = row >> 11, n = row & (NSEQ - 1);
                    int which = col >> 10, rem = col & 1023;
                    int h = rem >> 6, d = rem & 63;
                    size_t idx = (((size_t)(b * H_ + h)) * NSEQ + n) * HD_ + d;
                    if (which == 0)
                        *(float2*)&g_Q[idx] = make_float2(v0 * SCALE_F, v1 * SCALE_F);
                    else if (which == 1)
                        *(float2*)&g_K[idx] = make_float2(v0, v1);
                    else
                        *(float2*)&g_V[idx] = make_float2(v0, v1);
                }
            }
        }
    }
}

// ---------------------------------------------------------------------------
// Flash focal attention, split-bf16 + ldmatrix, double-buffered K/V,
// pass-reordered mmas for ILP.
// ---------------------------------------------------------------------------
#define FQH 0
#define FQL 4608
#define FPH 9216
#define FPL 13824
#define FKH 18432
#define FKL 23040
#define FVH 27648
#define FVL 32256
#define FKVB 2304                  // per-buffer stride (64*36)
#define FLASH_SMEM (36864*4)       // 147456 B

__global__ __launch_bounds__(256)
void flash_kernel(const float* __restrict__ falpha, const float* __restrict__ fgamma)
{
    extern __shared__ __align__(16) uint32_t smu[];
    const uint32_t sb = smem_u32(smu);
    const int tid = threadIdx.x, wid = tid >> 5, lane = tid & 31;
    const int g = lane >> 2, tg = lane & 3;
    const int bh = blockIdx.y, q0 = blockIdx.x * 128;
    const int qb = wid * 16;

    const float gam = fgamma[0], alpha = falpha[0];
    const bool g2 = (gam == 2.0f);

    const float* Qg = g_Q + ((size_t)bh * NSEQ + q0) * HD_;
    const float* Kg = g_K + (size_t)bh * NSEQ * HD_;
    const float* Vg = g_V + (size_t)bh * NSEQ * HD_;

    const int r16 = lane & 15;
    const int kA  = (lane >> 4) * 4;
    const int rK  = (lane & 7) + ((lane >> 4) << 3);
    const int kB  = ((lane >> 3) & 1) * 4;

    // ---- Q tile: load + split + packed store (once) ----
    {
        int r = tid >> 1, half = tid & 1;
        const float* qp = Qg + (size_t)r * HD_ + half * 32;
#pragma unroll
        for (int j = 0; j < 8; j++) {
            float4 v = *(const float4*)(qp + 4 * j);
            uint32_t hi[2], lo[2];
            split4(v, hi, lo);
            int k2 = half * 16 + 2 * j;
            *(uint2*)&smu[FQH + r * 36 + k2] = make_uint2(hi[0], hi[1]);
            *(uint2*)&smu[FQL + r * 36 + k2] = make_uint2(lo[0], lo[1]);
        }
    }

    const int kr = tid >> 2, kq4 = tid & 3;
    float4 k4[4], v4[4];
    auto ldgKV = [&](int ch) {
        const float* kp = Kg + (size_t)(ch * 64 + kr) * HD_ + kq4 * 16;
        const float* vp = Vg + (size_t)(ch * 64 + kr) * HD_ + kq4 * 16;
#pragma unroll
        for (int j = 0; j < 4; j++) {
            k4[j] = *(const float4*)(kp + 4 * j);
            v4[j] = *(const float4*)(vp + 4 * j);
        }
    };
    auto stsKV = [&](int buf) {
        const int bo = buf * FKVB;
#pragma unroll
        for (int j = 0; j < 4; j++) {
            uint32_t hi[2], lo[2];
            int k2 = kq4 * 8 + 2 * j;
            split4(k4[j], hi, lo);
            *(uint2*)&smu[FKH + bo + kr * 36 + k2] = make_uint2(hi[0], hi[1]);
            *(uint2*)&smu[FKL + bo + kr * 36 + k2] = make_uint2(lo[0], lo[1]);
            split4(v4[j], hi, lo);
            *(uint2*)&smu[FVH + bo + kr * 36 + k2] = make_uint2(hi[0], hi[1]);
            *(uint2*)&smu[FVL + bo + kr * 36 + k2] = make_uint2(lo[0], lo[1]);
        }
    };

    ldgKV(0); stsKV(0);
    __syncthreads();

    float o[8][4];
#pragma unroll
    for (int nt = 0; nt < 8; nt++) { o[nt][0] = o[nt][1] = o[nt][2] = o[nt][3] = 0.f; }
    float m0 = -1e30f, m1 = -1e30f, Z0 = 0.f, Z1 = 0.f, S20 = 0.f, S21 = 0.f;

    for (int ch = 0; ch < 32; ch++) {
        if (ch < 31) ldgKV(ch + 1);
        const uint32_t bko = (uint32_t)(ch & 1) * FKVB;

        // ---- S = Q K^T (pass-ordered) ----
        float s[8][4];
#pragma unroll
        for (int nt = 0; nt < 8; nt++) { s[nt][0] = s[nt][1] = s[nt][2] = s[nt][3] = 0.f; }
#pragma unroll
        for (int ks = 0; ks < 4; ks++) {
            const int kb = ks * 8;
            uint32_t qh[4], ql[4];
            ldmx4(qh, sb + (uint32_t)(FQH + (qb + r16) * 36 + kb + kA) * 4);
            ldmx4(ql, sb + (uint32_t)(FQL + (qb + r16) * 36 + kb + kA) * 4);
            uint32_t th[4][4], tl[4][4];
#pragma unroll
            for (int ntp = 0; ntp < 4; ntp++) {
                ldmx4(th[ntp], sb + (uint32_t)(FKH + bko + (rK + ntp * 16) * 36 + kb + kB) * 4);
                ldmx4(tl[ntp], sb + (uint32_t)(FKL + bko + (rK + ntp * 16) * 36 + kb + kB) * 4);
            }
#pragma unroll
            for (int ntp = 0; ntp < 4; ntp++) {
                mma16(s[2*ntp],   qh, &th[ntp][0]);
                mma16(s[2*ntp+1], qh, &th[ntp][2]);
            }
#pragma unroll
            for (int ntp = 0; ntp < 4; ntp++) {
                mma16(s[2*ntp],   qh, &tl[ntp][0]);
                mma16(s[2*ntp+1], qh, &tl[ntp][2]);
            }
#pragma unroll
            for (int ntp = 0; ntp < 4; ntp++) {
                mma16(s[2*ntp],   ql, &th[ntp][0]);
                mma16(s[2*ntp+1], ql, &th[ntp][2]);
            }
        }

        // ---- chunk max per row (quad reduce) ----
        float cm0 = -1e30f, cm1 = -1e30f;
#pragma unroll
        for (int nt = 0; nt < 8; nt++) {
            cm0 = fmaxf(cm0, fmaxf(s[nt][0], s[nt][1]));
            cm1 = fmaxf(cm1, fmaxf(s[nt][2], s[nt][3]));
        }
        cm0 = fmaxf(cm0, __shfl_xor_sync(0xffffffffu, cm0, 1));
        cm0 = fmaxf(cm0, __shfl_xor_sync(0xffffffffu, cm0, 2));
        cm1 = fmaxf(cm1, __shfl_xor_sync(0xffffffffu, cm1, 1));
        cm1 = fmaxf(cm1, __shfl_xor_sync(0xffffffffu, cm1, 2));

        // ---- online rescale ----
        float nm0 = fmaxf(m0, cm0), nm1 = fmaxf(m1, cm1);
        float cz0 = __expf(m0 - nm0), cz1 = __expf(m1 - nm1);
        float cw0 = g2 ? cz0 * cz0 : __expf(gam * (m0 - nm0));
        float cw1 = g2 ? cz1 * cz1 : __expf(gam * (m1 - nm1));
        Z0 *= cz0; Z1 *= cz1; S20 *= cw0; S21 *= cw1; m0 = nm0; m1 = nm1;
#pragma unroll
        for (int nt = 0; nt < 8; nt++) {
            o[nt][0] *= cw0; o[nt][1] *= cw0; o[nt][2] *= cw1; o[nt][3] *= cw1;
        }

        // ---- weights + packed P store (warp-private rows) ----
        float zp0 = 0.f, zp1 = 0.f, wp0 = 0.f, wp1 = 0.f;
#pragma unroll
        for (int nt = 0; nt < 8; nt++) {
            float e0 = __expf(s[nt][0] - m0), e1 = __expf(s[nt][1] - m0);
            float e2 = __expf(s[nt][2] - m1), e3 = __expf(s[nt][3] - m1);
            zp0 += e0 + e1; zp1 += e2 + e3;
            float w0, w1, w2, w3;
            if (g2) { w0 = e0 * e0; w1 = e1 * e1; w2 = e2 * e2; w3 = e3 * e3; }
            else {
                w0 = __expf(gam * (s[nt][0] - m0)); w1 = __expf(gam * (s[nt][1] - m0));
                w2 = __expf(gam * (s[nt][2] - m1)); w3 = __expf(gam * (s[nt][3] - m1));
            }
            wp0 += w0 + w1; wp1 += w2 + w3;
            int k2 = nt * 4 + tg;
            smu[FPH + (qb + g) * 36 + k2]     = packhi2(w0, w1);
            smu[FPL + (qb + g) * 36 + k2]     = packlo2(w0, w1);
            smu[FPH + (qb + g + 8) * 36 + k2] = packhi2(w2, w3);
            smu[FPL + (qb + g + 8) * 36 + k2] = packlo2(w2, w3);
        }
        Z0 += zp0; Z1 += zp1; S20 += wp0; S21 += wp1;
        __syncwarp();

        // ---- O += P V (pass-ordered) ----
#pragma unroll
        for (int ks = 0; ks < 4; ks++) {
            const int kb = ks * 8;
            const int k0 = ks * 16;
            uint32_t ph[4], pl[4];
            ldmx4(ph, sb + (uint32_t)(FPH + (qb + r16) * 36 + kb + kA) * 4);
            ldmx4(pl, sb + (uint32_t)(FPL + (qb + r16) * 36 + kb + kA) * 4);
            uint32_t th[4][4], tl[4][4];
#pragma unroll
            for (int dp = 0; dp < 4; dp++) {
                ldmx4t(th[dp], sb + (uint32_t)(FVH + bko + (k0 + r16) * 36 + dp * 8 + kA) * 4);
                ldmx4t(tl[dp], sb + (uint32_t)(FVL + bko + (k0 + r16) * 36 + dp * 8 + kA) * 4);
            }
#pragma unroll
            for (int dp = 0; dp < 4; dp++) {
                mma16(o[2*dp],   ph, &th[dp][0]);
                mma16(o[2*dp+1], ph, &th[dp][2]);
            }
#pragma unroll
            for (int dp = 0; dp < 4; dp++) {
                mma16(o[2*dp],   ph, &tl[dp][0]);
                mma16(o[2*dp+1], ph, &tl[dp][2]);
            }
#pragma unroll
            for (int dp = 0; dp < 4; dp++) {
                mma16(o[2*dp],   pl, &th[dp][0]);
                mma16(o[2*dp+1], pl, &th[dp][2]);
            }
        }

        if (ch < 31) { stsKV((ch + 1) & 1); __syncthreads(); }
    }

    // ---- final reduce + write ----
    Z0  += __shfl_xor_sync(0xffffffffu, Z0, 1);  Z0  += __shfl_xor_sync(0xffffffffu, Z0, 2);
    Z1  += __shfl_xor_sync(0xffffffffu, Z1, 1);  Z1  += __shfl_xor_sync(0xffffffffu, Z1, 2);
    S20 += __shfl_xor_sync(0xffffffffu, S20, 1); S20 += __shfl_xor_sync(0xffffffffu, S20, 2);
    S21 += __shfl_xor_sync(0xffffffffu, S21, 1); S21 += __shfl_xor_sync(0xffffffffu, S21, 2);

    float Zg0 = g2 ? Z0 * Z0 : __powf(Z0, gam);
    float Zg1 = g2 ? Z1 * Z1 : __powf(Z1, gam);
    float sc0 = alpha / (alpha * S20 + 1e-6f * Zg0);
    float sc1 = alpha / (alpha * S21 + 1e-6f * Zg1);

    const int b = bh >> 4, h = bh & 15;
    const int qA = q0 + qb + g, qB = qA + 8;
#pragma unroll
    for (int nt = 0; nt < 8; nt++) {
        int d = nt * 8 + 2 * tg;
        *(float2*)&g_AO[((size_t)b * NSEQ + qA) * DIM_ + h * HD_ + d] =
            make_float2(o[nt][0] * sc0, o[nt][1] * sc0);
        *(float2*)&g_AO[((size_t)b * NSEQ + qB) * DIM_ + h * HD_ + d] =
            make_float2(o[nt][2] * sc1, o[nt][3] * sc1);
    }
}

// ---------------------------------------------------------------------------
extern "C" void kernel_launch(void* const* d_in, const int* in_sizes, int n_in,
                              void* d_out, int out_size)
{
    const float* x = nullptr, *Wqkv = nullptr, *bqkv = nullptr;
    const float* Wproj = nullptr, *bproj = nullptr, *fa = nullptr, *fg = nullptr;
    for (int i = 0; i < n_in; i++) {
        int sz = in_sizes[i];
        const float* p = (const float*)d_in[i];
        if      (sz == B_*NSEQ*DIM_)   x = p;
        else if (sz == 3*DIM_*DIM_)    Wqkv = p;
        else if (sz == 3*DIM_)         bqkv = p;
        else if (sz == DIM_*DIM_)      Wproj = p;
        else if (sz == DIM_)           bproj = p;
        else if (sz == 1)              { if (!fa) fa = p; else fg = p; }
    }
    float* out = (float*)d_out;

    cudaFuncSetAttribute(tc_gemm<0>,   cudaFuncAttributeMaxDynamicSharedMemorySize, GEMM_SMEM);
    cudaFuncSetAttribute(tc_gemm<1>,   cudaFuncAttributeMaxDynamicSharedMemorySize, GEMM_SMEM);
    cudaFuncSetAttribute(flash_kernel, cudaFuncAttributeMaxDynamicSharedMemorySize, FLASH_SMEM);

    // 1) Fused QKV projection -> Q(scaled)/K/V
    tc_gemm<0><<<dim3(3*DIM_/128, (B_*NSEQ)/128), 256, GEMM_SMEM>>>(x, Wqkv, bqkv, nullptr);
    // 2) Focal flash attention -> g_AO
    flash_kernel<<<dim3(NSEQ/128, B_*H_), 256, FLASH_SMEM>>>(fa, fg);
    // 3) Output projection
    tc_gemm<1><<<dim3(DIM_/128, (B_*NSEQ)/128), 256, GEMM_SMEM>>>(nullptr, Wproj, bproj, out);
}

// round 7
// speedup vs baseline: 1.1835x; 1.1835x over previous
#include <cuda_runtime.h>
#include <cstdint>

// Problem constants
#define B_    2
#define NSEQ  2048
#define DIM_  1024
#define H_    16
#define HD_   64
#define SCALE_F 0.125f   // HD^-0.5

// ---------------------------------------------------------------------------
// Packed split storage: uint32 = {bf16 elem k (low), bf16 elem k+1 (high)}.
// hi = top16 of fp32; lo = bf16(x - hi).  A*B ~= Ah*Bh + Ah*Bl + Al*Bh.
// ---------------------------------------------------------------------------
__device__ __align__(16) uint32_t g_xh [4096*512], g_xl [4096*512];
__device__ __align__(16) uint32_t g_Wqh[3072*512], g_Wql[3072*512];
__device__ __align__(16) uint32_t g_Wph[1024*512], g_Wpl[1024*512];
#define QKV_W (B_*H_*NSEQ*32)
__device__ __align__(16) uint32_t g_Qh[QKV_W], g_Ql[QKV_W];
__device__ __align__(16) uint32_t g_Kh[QKV_W], g_Kl[QKV_W];
__device__ __align__(16) uint32_t g_Vh[QKV_W], g_Vl[QKV_W];
__device__ __align__(16) uint32_t g_AOh[4096*512], g_AOl[4096*512];

// ---------------------------------------------------------------------------
__device__ __forceinline__ uint32_t packhi2(float x, float y) {
    return __byte_perm(__float_as_uint(x), __float_as_uint(y), 0x7632);
}
__device__ __forceinline__ uint32_t packlo2(float x, float y) {
    float lx = x - __uint_as_float(__float_as_uint(x) & 0xffff0000u);
    float ly = y - __uint_as_float(__float_as_uint(y) & 0xffff0000u);
    return __byte_perm(__float_as_uint(lx), __float_as_uint(ly), 0x7632);
}
__device__ __forceinline__ uint32_t smem_u32(const void* p) {
    uint32_t a;
    asm("{ .reg .u64 t; cvta.to.shared.u64 t, %1; cvt.u32.u64 %0, t; }" : "=r"(a) : "l"(p));
    return a;
}
__device__ __forceinline__ void cp16(uint32_t s, const void* g) {
    asm volatile("cp.async.cg.shared.global [%0], [%1], 16;" :: "r"(s), "l"(g));
}
#define CP_COMMIT() asm volatile("cp.async.commit_group;" ::: "memory")
#define CP_WAIT1()  asm volatile("cp.async.wait_group 1;" ::: "memory")

__device__ __forceinline__ void mma16(float* c, const uint32_t* a, const uint32_t* b) {
    asm("mma.sync.aligned.m16n8k16.row.col.f32.bf16.bf16.f32 "
        "{%0,%1,%2,%3}, {%4,%5,%6,%7}, {%8,%9}, {%0,%1,%2,%3};"
        : "+f"(c[0]), "+f"(c[1]), "+f"(c[2]), "+f"(c[3])
        : "r"(a[0]), "r"(a[1]), "r"(a[2]), "r"(a[3]), "r"(b[0]), "r"(b[1]));
}
__device__ __forceinline__ void ldmx4(uint32_t* r, uint32_t a) {
    asm volatile("ldmatrix.sync.aligned.m8n8.x4.shared.b16 {%0,%1,%2,%3}, [%4];"
        : "=r"(r[0]), "=r"(r[1]), "=r"(r[2]), "=r"(r[3]) : "r"(a));
}
__device__ __forceinline__ void ldmx4t(uint32_t* r, uint32_t a) {
    asm volatile("ldmatrix.sync.aligned.m8n8.x4.trans.shared.b16 {%0,%1,%2,%3}, [%4];"
        : "=r"(r[0]), "=r"(r[1]), "=r"(r[2]), "=r"(r[3]) : "r"(a));
}
// XOR swizzles (word offsets). Conflict-free for 8 aligned rows per ldmatrix phase.
__device__ __forceinline__ int sw16(int r, int c) { return r * 16 + 4 * (c ^ ((r >> 1) & 3)); }
__device__ __forceinline__ int sw32(int r, int c) { return r * 32 + 4 * (c ^ (r & 7)); }

// ---------------------------------------------------------------------------
// Prep: split fp32 tensor into packed hi/lo arrays. which: 0=x 1=Wqkv 2=Wproj.
// ---------------------------------------------------------------------------
__global__ __launch_bounds__(256)
void split_kernel(const float4* __restrict__ src, int which, int n4)
{
    uint2 *h, *l;
    if (which == 0)      { h = (uint2*)g_xh;  l = (uint2*)g_xl;  }
    else if (which == 1) { h = (uint2*)g_Wqh; l = (uint2*)g_Wql; }
    else                 { h = (uint2*)g_Wph; l = (uint2*)g_Wpl; }
    int i = blockIdx.x * 256 + threadIdx.x;
    if (i < n4) {
        float4 v = src[i];
        h[i] = make_uint2(packhi2(v.x, v.y), packhi2(v.z, v.w));
        l[i] = make_uint2(packlo2(v.x, v.y), packlo2(v.z, v.w));
    }
}

// ---------------------------------------------------------------------------
// Split-bf16 GEMM on pre-split packed inputs. CTA 128x128, 8 warps (2x4,
// warp 64x32), BK=32, cp.async, 3 smem buffers, 1 sync/chunk, 2 CTAs/SM.
// Buffer word layout: [AH][AL][BH][BL] each 128x16 words, XOR-swizzled.
// MODE 0: x @ Wqkv^T -> packed Q(scaled)/K/V.  MODE 1: AO @ Wproj^T -> fp32 C.
// ---------------------------------------------------------------------------
#define GARRW 2048
#define GBUFW (4*GARRW)
#define GEMM_SMEM (3*GBUFW*4)   // 98304 B

template<int MODE>
__global__ __launch_bounds__(256, 2)
void tc_gemm(const float* __restrict__ bias, float* __restrict__ C)
{
    extern __shared__ __align__(16) uint32_t smu[];
    const uint32_t sb = smem_u32(smu);

    const uint32_t *Ah, *Al, *Bh, *Bl;
    if (MODE == 0) { Ah = g_xh;  Al = g_xl;  Bh = g_Wqh; Bl = g_Wql; }
    else           { Ah = g_AOh; Al = g_AOl; Bh = g_Wph; Bl = g_Wpl; }

    const int tid = threadIdx.x, wid = tid >> 5, lane = tid & 31;
    const int g = lane >> 2, tg = lane & 3;
    const int wm = wid >> 2, wn = wid & 3;
    const int row0 = blockIdx.y * 128, col0 = blockIdx.x * 128;

    const int rA = wm * 64 + (lane & 15);
    const int selA = lane >> 4;
    const int rB = wn * 32 + (lane & 7) + ((lane >> 4) << 3);
    const int selB = (lane >> 3) & 1;

    float c[4][4][4];
#pragma unroll
    for (int mt = 0; mt < 4; mt++)
#pragma unroll
        for (int nt = 0; nt < 4; nt++) {
            c[mt][nt][0] = 0.f; c[mt][nt][1] = 0.f; c[mt][nt][2] = 0.f; c[mt][nt][3] = 0.f;
        }

    const int lr = tid >> 1, half = tid & 1;
    auto cpload = [&](int ch, int buf) {
        const uint32_t bo = (uint32_t)buf * GBUFW;
        const size_t aw = (size_t)(row0 + lr) * 512 + ch * 16 + half * 8;
        const size_t bw = (size_t)(col0 + lr) * 512 + ch * 16 + half * 8;
#pragma unroll
        for (int j = 0; j < 2; j++) {
            uint32_t d = bo + sw16(lr, half * 2 + j);
            cp16(sb + 4 * d,                Ah + aw + 4 * j);
            cp16(sb + 4 * (d + GARRW),      Al + aw + 4 * j);
            cp16(sb + 4 * (d + 2 * GARRW),  Bh + bw + 4 * j);
            cp16(sb + 4 * (d + 3 * GARRW),  Bl + bw + 4 * j);
        }
    };

    cpload(0, 0); CP_COMMIT();
    cpload(1, 1); CP_COMMIT();

    for (int ch = 0; ch < 32; ch++) {
        CP_WAIT1();
        __syncthreads();
        if (ch + 2 < 32) cpload(ch + 2, (ch + 2) % 3);
        CP_COMMIT();

        const uint32_t bufb = sb + 4u * (uint32_t)((ch % 3) * GBUFW);
#pragma unroll
        for (int ks = 0; ks < 2; ks++) {
            const int cA = 2 * ks + selA;
            const int cB = 2 * ks + selB;
            uint32_t ah[4][4], al[4][4];
#pragma unroll
            for (int mt = 0; mt < 4; mt++) {
                ldmx4(ah[mt], bufb + 4u * (uint32_t)sw16(rA + mt * 16, cA));
                ldmx4(al[mt], bufb + 4u * (uint32_t)(GARRW + sw16(rA + mt * 16, cA)));
            }
#pragma unroll
            for (int ntp = 0; ntp < 2; ntp++) {
                uint32_t th[4], tl[4];
                ldmx4(th, bufb + 4u * (uint32_t)(2 * GARRW + sw16(rB + ntp * 16, cB)));
                ldmx4(tl, bufb + 4u * (uint32_t)(3 * GARRW + sw16(rB + ntp * 16, cB)));
                // hi*hi (8 indep), hi*lo (8), lo*hi (8)
#pragma unroll
                for (int mt = 0; mt < 4; mt++) mma16(c[mt][2*ntp],   ah[mt], &th[0]);
#pragma unroll
                for (int mt = 0; mt < 4; mt++) mma16(c[mt][2*ntp+1], ah[mt], &th[2]);
#pragma unroll
                for (int mt = 0; mt < 4; mt++) mma16(c[mt][2*ntp],   ah[mt], &tl[0]);
#pragma unroll
                for (int mt = 0; mt < 4; mt++) mma16(c[mt][2*ntp+1], ah[mt], &tl[2]);
#pragma unroll
                for (int mt = 0; mt < 4; mt++) mma16(c[mt][2*ntp],   al[mt], &th[0]);
#pragma unroll
                for (int mt = 0; mt < 4; mt++) mma16(c[mt][2*ntp+1], al[mt], &th[2]);
            }
        }
    }

    // Epilogue
#pragma unroll
    for (int mt = 0; mt < 4; mt++) {
#pragma unroll
        for (int hf = 0; hf < 2; hf++) {
            int row = row0 + wm * 64 + mt * 16 + g + hf * 8;
#pragma unroll
            for (int nt = 0; nt < 4; nt++) {
                int col = col0 + wn * 32 + nt * 8 + 2 * tg;
                float v0 = c[mt][nt][hf * 2 + 0] + bias[col];
                float v1 = c[mt][nt][hf * 2 + 1] + bias[col + 1];
                if (MODE == 1) {
                    *(float2*)&C[(size_t)row * DIM_ + col] = make_float2(v0, v1);
                } else {
                    int b = row >> 11, n = row & (NSEQ - 1);
                    int which = col >> 10, rem = col & 1023;
                    int h = rem >> 6, d = rem & 63;
                    size_t w = (((size_t)(b * H_ + h)) * NSEQ + n) * 32 + (d >> 1);
                    if (which == 0) {
                        v0 *= SCALE_F; v1 *= SCALE_F;
                        g_Qh[w] = packhi2(v0, v1); g_Ql[w] = packlo2(v0, v1);
                    } else if (which == 1) {
                        g_Kh[w] = packhi2(v0, v1); g_Kl[w] = packlo2(v0, v1);
                    } else {
                        g_Vh[w] = packhi2(v0, v1); g_Vl[w] = packlo2(v0, v1);
                    }
                }
            }
        }
    }
}

// ---------------------------------------------------------------------------
// Flash focal attention on pre-split packed Q/K/V. cp.async, 3-buffer K/V,
// 1 sync/chunk, XOR-swizzled smem, split-bf16 mma via ldmatrix.
// Word offsets: QH 0, QL 4096, PH 8192, PL 12288, KV base 16384
// (per buffer: KH +0, KL +2048, VH +4096, VL +6144; buffer stride 8192).
// ---------------------------------------------------------------------------
#define FQH 0
#define FQL 4096
#define FPH 8192
#define FPL 12288
#define FKV 16384
#define FKVB 8192
#define FLASH_SMEM ((16384 + 3*FKVB)*4)   // 163840 B

__global__ __launch_bounds__(256)
void flash_kernel(const float* __restrict__ falpha, const float* __restrict__ fgamma)
{
    extern __shared__ __align__(16) uint32_t smu[];
    const uint32_t sb = smem_u32(smu);
    const int tid = threadIdx.x, wid = tid >> 5, lane = tid & 31;
    const int g = lane >> 2, tg = lane & 3;
    const int bh = blockIdx.y, q0 = blockIdx.x * 128;
    const int qb = wid * 16;

    const float gam = fgamma[0], alpha = falpha[0];
    const bool g2 = (gam == 2.0f);

    const int r16 = lane & 15;
    const int sel = lane >> 4;
    const int rK  = (lane & 7) + ((lane >> 4) << 3);
    const int selB = (lane >> 3) & 1;

    // cp.async staging maps
    auto cpQ = [&]() {
        int r = tid >> 1, hf = tid & 1;
        size_t src = ((size_t)bh * NSEQ + q0 + r) * 32 + hf * 16;
#pragma unroll
        for (int j = 0; j < 4; j++) {
            uint32_t d = (uint32_t)sw32(r, hf * 4 + j);
            cp16(sb + 4 * (FQH + d), g_Qh + src + 4 * j);
            cp16(sb + 4 * (FQL + d), g_Ql + src + 4 * j);
        }
    };
    auto cpKV = [&](int ch, int buf) {
        int r = tid >> 2, q4 = tid & 3;
        size_t src = ((size_t)bh * NSEQ + ch * 64 + r) * 32 + q4 * 8;
        uint32_t bo = FKV + (uint32_t)buf * FKVB;
#pragma unroll
        for (int j = 0; j < 2; j++) {
            uint32_t d = bo + (uint32_t)sw32(r, q4 * 2 + j);
            cp16(sb + 4 * d,           g_Kh + src + 4 * j);
            cp16(sb + 4 * (d + 2048),  g_Kl + src + 4 * j);
            cp16(sb + 4 * (d + 4096),  g_Vh + src + 4 * j);
            cp16(sb + 4 * (d + 6144),  g_Vl + src + 4 * j);
        }
    };

    cpQ(); cpKV(0, 0); CP_COMMIT();
    cpKV(1, 1);        CP_COMMIT();

    float o[8][4];
#pragma unroll
    for (int nt = 0; nt < 8; nt++) { o[nt][0] = o[nt][1] = o[nt][2] = o[nt][3] = 0.f; }
    float m0 = -1e30f, m1 = -1e30f, Z0 = 0.f, Z1 = 0.f, S20 = 0.f, S21 = 0.f;

    for (int ch = 0; ch < 32; ch++) {
        CP_WAIT1();
        __syncthreads();
        if (ch + 2 < 32) cpKV(ch + 2, (ch + 2) % 3);
        CP_COMMIT();

        const uint32_t kvb = FKV + (uint32_t)((ch % 3) * FKVB);

        // ---- S = Q K^T ----
        float s[8][4];
#pragma unroll
        for (int nt = 0; nt < 8; nt++) { s[nt][0] = s[nt][1] = s[nt][2] = s[nt][3] = 0.f; }
#pragma unroll
        for (int ks = 0; ks < 4; ks++) {
            const int cA = 2 * ks + sel;
            const int cB = 2 * ks + selB;
            uint32_t qh[4], ql[4];
            ldmx4(qh, sb + 4u * (uint32_t)(FQH + sw32(qb + r16, cA)));
            ldmx4(ql, sb + 4u * (uint32_t)(FQL + sw32(qb + r16, cA)));
#pragma unroll
            for (int np = 0; np < 2; np++) {
                const int n0 = np * 2;
                uint32_t th0[4], th1[4], tl0[4], tl1[4];
                ldmx4(th0, sb + 4u * (uint32_t)(kvb + sw32(rK + n0 * 16, cB)));
                ldmx4(th1, sb + 4u * (uint32_t)(kvb + sw32(rK + (n0 + 1) * 16, cB)));
                ldmx4(tl0, sb + 4u * (uint32_t)(kvb + 2048 + sw32(rK + n0 * 16, cB)));
                ldmx4(tl1, sb + 4u * (uint32_t)(kvb + 2048 + sw32(rK + (n0 + 1) * 16, cB)));
                mma16(s[2*n0],   qh, &th0[0]); mma16(s[2*n0+1], qh, &th0[2]);
                mma16(s[2*n0+2], qh, &th1[0]); mma16(s[2*n0+3], qh, &th1[2]);
                mma16(s[2*n0],   qh, &tl0[0]); mma16(s[2*n0+1], qh, &tl0[2]);
                mma16(s[2*n0+2], qh, &tl1[0]); mma16(s[2*n0+3], qh, &tl1[2]);
                mma16(s[2*n0],   ql, &th0[0]); mma16(s[2*n0+1], ql, &th0[2]);
                mma16(s[2*n0+2], ql, &th1[0]); mma16(s[2*n0+3], ql, &th1[2]);
            }
        }

        // ---- chunk max per row (quad reduce) ----
        float cm0 = -1e30f, cm1 = -1e30f;
#pragma unroll
        for (int nt = 0; nt < 8; nt++) {
            cm0 = fmaxf(cm0, fmaxf(s[nt][0], s[nt][1]));
            cm1 = fmaxf(cm1, fmaxf(s[nt][2], s[nt][3]));
        }
        cm0 = fmaxf(cm0, __shfl_xor_sync(0xffffffffu, cm0, 1));
        cm0 = fmaxf(cm0, __shfl_xor_sync(0xffffffffu, cm0, 2));
        cm1 = fmaxf(cm1, __shfl_xor_sync(0xffffffffu, cm1, 1));
        cm1 = fmaxf(cm1, __shfl_xor_sync(0xffffffffu, cm1, 2));

        // ---- online rescale ----
        float nm0 = fmaxf(m0, cm0), nm1 = fmaxf(m1, cm1);
        float cz0 = __expf(m0 - nm0), cz1 = __expf(m1 - nm1);
        float cw0 = g2 ? cz0 * cz0 : __expf(gam * (m0 - nm0));
        float cw1 = g2 ? cz1 * cz1 : __expf(gam * (m1 - nm1));
        Z0 *= cz0; Z1 *= cz1; S20 *= cw0; S21 *= cw1; m0 = nm0; m1 = nm1;
#pragma unroll
        for (int nt = 0; nt < 8; nt++) {
            o[nt][0] *= cw0; o[nt][1] *= cw0; o[nt][2] *= cw1; o[nt][3] *= cw1;
        }

        // ---- weights + packed P store (warp-private rows; swizzled) ----
        float zp0 = 0.f, zp1 = 0.f, wp0 = 0.f, wp1 = 0.f;
#pragma unroll
        for (int nt = 0; nt < 8; nt++) {
            float e0 = __expf(s[nt][0] - m0), e1 = __expf(s[nt][1] - m0);
            float e2 = __expf(s[nt][2] - m1), e3 = __expf(s[nt][3] - m1);
            zp0 += e0 + e1; zp1 += e2 + e3;
            float w0, w1, w2, w3;
            if (g2) { w0 = e0 * e0; w1 = e1 * e1; w2 = e2 * e2; w3 = e3 * e3; }
            else {
                w0 = __expf(gam * (s[nt][0] - m0)); w1 = __expf(gam * (s[nt][1] - m0));
                w2 = __expf(gam * (s[nt][2] - m1)); w3 = __expf(gam * (s[nt][3] - m1));
            }
            wp0 += w0 + w1; wp1 += w2 + w3;
            smu[FPH + sw32(qb + g, nt) + tg]     = packhi2(w0, w1);
            smu[FPL + sw32(qb + g, nt) + tg]     = packlo2(w0, w1);
            smu[FPH + sw32(qb + g + 8, nt) + tg] = packhi2(w2, w3);
            smu[FPL + sw32(qb + g + 8, nt) + tg] = packlo2(w2, w3);
        }
        Z0 += zp0; Z1 += zp1; S20 += wp0; S21 += wp1;
        __syncwarp();

        // ---- O += P V ----
#pragma unroll
        for (int ks = 0; ks < 4; ks++) {
            const int cP = 2 * ks + sel;
            const int k0 = ks * 16;
            uint32_t ph[4], pl[4];
            ldmx4(ph, sb + 4u * (uint32_t)(FPH + sw32(qb + r16, cP)));
            ldmx4(pl, sb + 4u * (uint32_t)(FPL + sw32(qb + r16, cP)));
#pragma unroll
            for (int dp2 = 0; dp2 < 2; dp2++) {
                const int d0 = dp2 * 2;
                uint32_t th0[4], th1[4], tl0[4], tl1[4];
                ldmx4t(th0, sb + 4u * (uint32_t)(kvb + 4096 + sw32(k0 + r16, d0 * 2 + sel)));
                ldmx4t(th1, sb + 4u * (uint32_t)(kvb + 4096 + sw32(k0 + r16, (d0 + 1) * 2 + sel)));
                ldmx4t(tl0, sb + 4u * (uint32_t)(kvb + 6144 + sw32(k0 + r16, d0 * 2 + sel)));
                ldmx4t(tl1, sb + 4u * (uint32_t)(kvb + 6144 + sw32(k0 + r16, (d0 + 1) * 2 + sel)));
                mma16(o[2*d0],   ph, &th0[0]); mma16(o[2*d0+1], ph, &th0[2]);
                mma16(o[2*d0+2], ph, &th1[0]); mma16(o[2*d0+3], ph, &th1[2]);
                mma16(o[2*d0],   ph, &tl0[0]); mma16(o[2*d0+1], ph, &tl0[2]);
                mma16(o[2*d0+2], ph, &tl1[0]); mma16(o[2*d0+3], ph, &tl1[2]);
                mma16(o[2*d0],   pl, &th0[0]); mma16(o[2*d0+1], pl, &th0[2]);
                mma16(o[2*d0+2], pl, &th1[0]); mma16(o[2*d0+3], pl, &th1[2]);
            }
        }
    }

    // ---- final reduce + packed split write of AO ----
    Z0  += __shfl_xor_sync(0xffffffffu, Z0, 1);  Z0  += __shfl_xor_sync(0xffffffffu, Z0, 2);
    Z1  += __shfl_xor_sync(0xffffffffu, Z1, 1);  Z1  += __shfl_xor_sync(0xffffffffu, Z1, 2);
    S20 += __shfl_xor_sync(0xffffffffu, S20, 1); S20 += __shfl_xor_sync(0xffffffffu, S20, 2);
    S21 += __shfl_xor_sync(0xffffffffu, S21, 1); S21 += __shfl_xor_sync(0xffffffffu, S21, 2);

    float Zg0 = g2 ? Z0 * Z0 : __powf(Z0, gam);
    float Zg1 = g2 ? Z1 * Z1 : __powf(Z1, gam);
    float sc0 = alpha / (alpha * S20 + 1e-6f * Zg0);
    float sc1 = alpha / (alpha * S21 + 1e-6f * Zg1);

    const int b = bh >> 4, h = bh & 15;
    const int qA = q0 + qb + g, qB = qA + 8;
#pragma unroll
    for (int nt = 0; nt < 8; nt++) {
        int d = nt * 8 + 2 * tg;
        size_t wA = ((size_t)b * NSEQ + qA) * 512 + ((h * HD_ + d) >> 1);
        size_t wB = ((size_t)b * NSEQ + qB) * 512 + ((h * HD_ + d) >> 1);
        float a0 = o[nt][0] * sc0, a1 = o[nt][1] * sc0;
        float b0 = o[nt][2] * sc1, b1 = o[nt][3] * sc1;
        g_AOh[wA] = packhi2(a0, a1); g_AOl[wA] = packlo2(a0, a1);
        g_AOh[wB] = packhi2(b0, b1); g_AOl[wB] = packlo2(b0, b1);
    }
}

// ---------------------------------------------------------------------------
extern "C" void kernel_launch(void* const* d_in, const int* in_sizes, int n_in,
                              void* d_out, int out_size)
{
    const float* x = nullptr, *Wqkv = nullptr, *bqkv = nullptr;
    const float* Wproj = nullptr, *bproj = nullptr, *fa = nullptr, *fg = nullptr;
    for (int i = 0; i < n_in; i++) {
        int sz = in_sizes[i];
        const float* p = (const float*)d_in[i];
        if      (sz == B_*NSEQ*DIM_)   x = p;
        else if (sz == 3*DIM_*DIM_)    Wqkv = p;
        else if (sz == 3*DIM_)         bqkv = p;
        else if (sz == DIM_*DIM_)      Wproj = p;
        else if (sz == DIM_)           bproj = p;
        else if (sz == 1)              { if (!fa) fa = p; else fg = p; }
    }
    float* out = (float*)d_out;

    cudaFuncSetAttribute(tc_gemm<0>,   cudaFuncAttributeMaxDynamicSharedMemorySize, GEMM_SMEM);
    cudaFuncSetAttribute(tc_gemm<1>,   cudaFuncAttributeMaxDynamicSharedMemorySize, GEMM_SMEM);
    cudaFuncSetAttribute(flash_kernel, cudaFuncAttributeMaxDynamicSharedMemorySize, FLASH_SMEM);

    // 0) Split inputs into packed bf16 hi/lo
    split_kernel<<<4096, 256>>>((const float4*)x,     0, 4096*256);
    split_kernel<<<3072, 256>>>((const float4*)Wqkv,  1, 3072*256);
    split_kernel<<<1024, 256>>>((const float4*)Wproj, 2, 1024*256);
    // 1) Fused QKV projection -> packed Q(scaled)/K/V
    tc_gemm<0><<<dim3(3*DIM_/128, (B_*NSEQ)/128), 256, GEMM_SMEM>>>(bqkv, nullptr);
    // 2) Focal flash attention -> packed AO
    flash_kernel<<<dim3(NSEQ/128, B_*H_), 256, FLASH_SMEM>>>(fa, fg);
    // 3) Output projection -> d_out
    tc_gemm<1><<<dim3(DIM_/128, (B_*NSEQ)/128), 256, GEMM_SMEM>>>(bproj, out);
}

// round 8
// speedup vs baseline: 1.3127x; 1.1092x over previous
#include <cuda_runtime.h>
#include <cstdint>

// Problem constants
#define B_    2
#define NSEQ  2048
#define DIM_  1024
#define H_    16
#define HD_   64
#define SCALE_F 0.125f   // HD^-0.5

// ---------------------------------------------------------------------------
// Packed split storage: uint32 = {bf16 elem k (low), bf16 elem k+1 (high)}.
// hi = top16 of fp32; lo = bf16(x - hi).  A*B ~= Ah*Bh + Ah*Bl + Al*Bh.
// ---------------------------------------------------------------------------
__device__ __align__(16) uint32_t g_xh [4096*512], g_xl [4096*512];
__device__ __align__(16) uint32_t g_Wqh[3072*512], g_Wql[3072*512];
__device__ __align__(16) uint32_t g_Wph[1024*512], g_Wpl[1024*512];
#define QKV_W (B_*H_*NSEQ*32)
__device__ __align__(16) uint32_t g_Qh[QKV_W], g_Ql[QKV_W];
__device__ __align__(16) uint32_t g_Kh[QKV_W], g_Kl[QKV_W];
__device__ __align__(16) uint32_t g_Vh[QKV_W], g_Vl[QKV_W];
__device__ __align__(16) uint32_t g_AOh[4096*512], g_AOl[4096*512];

// ---------------------------------------------------------------------------
__device__ __forceinline__ uint32_t packhi2(float x, float y) {
    return __byte_perm(__float_as_uint(x), __float_as_uint(y), 0x7632);
}
__device__ __forceinline__ uint32_t packlo2(float x, float y) {
    float lx = x - __uint_as_float(__float_as_uint(x) & 0xffff0000u);
    float ly = y - __uint_as_float(__float_as_uint(y) & 0xffff0000u);
    return __byte_perm(__float_as_uint(lx), __float_as_uint(ly), 0x7632);
}
__device__ __forceinline__ uint32_t smem_u32(const void* p) {
    uint32_t a;
    asm("{ .reg .u64 t; cvta.to.shared.u64 t, %1; cvt.u32.u64 %0, t; }" : "=r"(a) : "l"(p));
    return a;
}
__device__ __forceinline__ void cp16(uint32_t s, const void* g) {
    asm volatile("cp.async.cg.shared.global [%0], [%1], 16;" :: "r"(s), "l"(g));
}
#define CP_COMMIT() asm volatile("cp.async.commit_group;" ::: "memory")
#define CP_WAIT1()  asm volatile("cp.async.wait_group 1;" ::: "memory")
#define CP_WAIT0()  asm volatile("cp.async.wait_group 0;" ::: "memory")

__device__ __forceinline__ void mma16(float* c, const uint32_t* a, const uint32_t* b) {
    asm("mma.sync.aligned.m16n8k16.row.col.f32.bf16.bf16.f32 "
        "{%0,%1,%2,%3}, {%4,%5,%6,%7}, {%8,%9}, {%0,%1,%2,%3};"
        : "+f"(c[0]), "+f"(c[1]), "+f"(c[2]), "+f"(c[3])
        : "r"(a[0]), "r"(a[1]), "r"(a[2]), "r"(a[3]), "r"(b[0]), "r"(b[1]));
}
__device__ __forceinline__ void ldmx4(uint32_t* r, uint32_t a) {
    asm volatile("ldmatrix.sync.aligned.m8n8.x4.shared.b16 {%0,%1,%2,%3}, [%4];"
        : "=r"(r[0]), "=r"(r[1]), "=r"(r[2]), "=r"(r[3]) : "r"(a));
}
__device__ __forceinline__ void ldmx4t(uint32_t* r, uint32_t a) {
    asm volatile("ldmatrix.sync.aligned.m8n8.x4.trans.shared.b16 {%0,%1,%2,%3}, [%4];"
        : "=r"(r[0]), "=r"(r[1]), "=r"(r[2]), "=r"(r[3]) : "r"(a));
}
// XOR swizzles (word offsets). Conflict-free per ldmatrix 8-row phase.
__device__ __forceinline__ int sw16(int r, int c) { return r * 16 + 4 * (c ^ ((r >> 1) & 3)); }
__device__ __forceinline__ int sw32(int r, int c) { return r * 32 + 4 * (c ^ (r & 7)); }

// ---------------------------------------------------------------------------
// Prep: split fp32 tensor into packed hi/lo arrays. which: 0=x 1=Wqkv 2=Wproj.
// ---------------------------------------------------------------------------
__global__ __launch_bounds__(256)
void split_kernel(const float4* __restrict__ src, int which, int n4)
{
    uint2 *h, *l;
    if (which == 0)      { h = (uint2*)g_xh;  l = (uint2*)g_xl;  }
    else if (which == 1) { h = (uint2*)g_Wqh; l = (uint2*)g_Wql; }
    else                 { h = (uint2*)g_Wph; l = (uint2*)g_Wpl; }
    int i = blockIdx.x * 256 + threadIdx.x;
    if (i < n4) {
        float4 v = src[i];
        h[i] = make_uint2(packhi2(v.x, v.y), packhi2(v.z, v.w));
        l[i] = make_uint2(packlo2(v.x, v.y), packlo2(v.z, v.w));
    }
}

// ---------------------------------------------------------------------------
// Split-bf16 GEMM on pre-split packed inputs (unchanged from R7).
// ---------------------------------------------------------------------------
#define GARRW 2048
#define GBUFW (4*GARRW)
#define GEMM_SMEM (3*GBUFW*4)   // 98304 B

template<int MODE>
__global__ __launch_bounds__(256, 2)
void tc_gemm(const float* __restrict__ bias, float* __restrict__ C)
{
    extern __shared__ __align__(16) uint32_t smu[];
    const uint32_t sb = smem_u32(smu);

    const uint32_t *Ah, *Al, *Bh, *Bl;
    if (MODE == 0) { Ah = g_xh;  Al = g_xl;  Bh = g_Wqh; Bl = g_Wql; }
    else           { Ah = g_AOh; Al = g_AOl; Bh = g_Wph; Bl = g_Wpl; }

    const int tid = threadIdx.x, wid = tid >> 5, lane = tid & 31;
    const int g = lane >> 2, tg = lane & 3;
    const int wm = wid >> 2, wn = wid & 3;
    const int row0 = blockIdx.y * 128, col0 = blockIdx.x * 128;

    const int rA = wm * 64 + (lane & 15);
    const int selA = lane >> 4;
    const int rB = wn * 32 + (lane & 7) + ((lane >> 4) << 3);
    const int selB = (lane >> 3) & 1;

    float c[4][4][4];
#pragma unroll
    for (int mt = 0; mt < 4; mt++)
#pragma unroll
        for (int nt = 0; nt < 4; nt++) {
            c[mt][nt][0] = 0.f; c[mt][nt][1] = 0.f; c[mt][nt][2] = 0.f; c[mt][nt][3] = 0.f;
        }

    const int lr = tid >> 1, half = tid & 1;
    auto cpload = [&](int ch, int buf) {
        const uint32_t bo = (uint32_t)buf * GBUFW;
        const size_t aw = (size_t)(row0 + lr) * 512 + ch * 16 + half * 8;
        const size_t bw = (size_t)(col0 + lr) * 512 + ch * 16 + half * 8;
#pragma unroll
        for (int j = 0; j < 2; j++) {
            uint32_t d = bo + sw16(lr, half * 2 + j);
            cp16(sb + 4 * d,                Ah + aw + 4 * j);
            cp16(sb + 4 * (d + GARRW),      Al + aw + 4 * j);
            cp16(sb + 4 * (d + 2 * GARRW),  Bh + bw + 4 * j);
            cp16(sb + 4 * (d + 3 * GARRW),  Bl + bw + 4 * j);
        }
    };

    cpload(0, 0); CP_COMMIT();
    cpload(1, 1); CP_COMMIT();

    for (int ch = 0; ch < 32; ch++) {
        CP_WAIT1();
        __syncthreads();
        if (ch + 2 < 32) cpload(ch + 2, (ch + 2) % 3);
        CP_COMMIT();

        const uint32_t bufb = sb + 4u * (uint32_t)((ch % 3) * GBUFW);
#pragma unroll
        for (int ks = 0; ks < 2; ks++) {
            const int cA = 2 * ks + selA;
            const int cB = 2 * ks + selB;
            uint32_t ah[4][4], al[4][4];
#pragma unroll
            for (int mt = 0; mt < 4; mt++) {
                ldmx4(ah[mt], bufb + 4u * (uint32_t)sw16(rA + mt * 16, cA));
                ldmx4(al[mt], bufb + 4u * (uint32_t)(GARRW + sw16(rA + mt * 16, cA)));
            }
#pragma unroll
            for (int ntp = 0; ntp < 2; ntp++) {
                uint32_t th[4], tl[4];
                ldmx4(th, bufb + 4u * (uint32_t)(2 * GARRW + sw16(rB + ntp * 16, cB)));
                ldmx4(tl, bufb + 4u * (uint32_t)(3 * GARRW + sw16(rB + ntp * 16, cB)));
#pragma unroll
                for (int mt = 0; mt < 4; mt++) mma16(c[mt][2*ntp],   ah[mt], &th[0]);
#pragma unroll
                for (int mt = 0; mt < 4; mt++) mma16(c[mt][2*ntp+1], ah[mt], &th[2]);
#pragma unroll
                for (int mt = 0; mt < 4; mt++) mma16(c[mt][2*ntp],   ah[mt], &tl[0]);
#pragma unroll
                for (int mt = 0; mt < 4; mt++) mma16(c[mt][2*ntp+1], ah[mt], &tl[2]);
#pragma unroll
                for (int mt = 0; mt < 4; mt++) mma16(c[mt][2*ntp],   al[mt], &th[0]);
#pragma unroll
                for (int mt = 0; mt < 4; mt++) mma16(c[mt][2*ntp+1], al[mt], &th[2]);
            }
        }
    }

    // Epilogue
#pragma unroll
    for (int mt = 0; mt < 4; mt++) {
#pragma unroll
        for (int hf = 0; hf < 2; hf++) {
            int row = row0 + wm * 64 + mt * 16 + g + hf * 8;
#pragma unroll
            for (int nt = 0; nt < 4; nt++) {
                int col = col0 + wn * 32 + nt * 8 + 2 * tg;
                float v0 = c[mt][nt][hf * 2 + 0] + bias[col];
                float v1 = c[mt][nt][hf * 2 + 1] + bias[col + 1];
                if (MODE == 1) {
                    *(float2*)&C[(size_t)row * DIM_ + col] = make_float2(v0, v1);
                } else {
                    int b = row >> 11, n = row & (NSEQ - 1);
                    int which = col >> 10, rem = col & 1023;
                    int h = rem >> 6, d = rem & 63;
                    size_t w = (((size_t)(b * H_ + h)) * NSEQ + n) * 32 + (d >> 1);
                    if (which == 0) {
                        v0 *= SCALE_F; v1 *= SCALE_F;
                        g_Qh[w] = packhi2(v0, v1); g_Ql[w] = packlo2(v0, v1);
                    } else if (which == 1) {
                        g_Kh[w] = packhi2(v0, v1); g_Kl[w] = packlo2(v0, v1);
                    } else {
                        g_Vh[w] = packhi2(v0, v1); g_Vl[w] = packlo2(v0, v1);
                    }
                }
            }
        }
    }
}

// ---------------------------------------------------------------------------
// Flash focal attention. P kept in REGISTERS (C-frag == A-frag layout), no P
// smem round-trip. Smem: Q hi/lo (static) + double-buffered K/V. 2 CTAs/SM.
// Word offsets: QH 0, QL 4096, KV 8192 (per buffer: KH+0 KL+2048 VH+4096
// VL+6144; buffer stride 8192).
// ---------------------------------------------------------------------------
#define FQH 0
#define FQL 4096
#define FKV 8192
#define FKVB 8192
#define FLASH_SMEM ((8192 + 2*FKVB)*4)   // 98304 B

__global__ __launch_bounds__(256, 2)
void flash_kernel(const float* __restrict__ falpha, const float* __restrict__ fgamma)
{
    extern __shared__ __align__(16) uint32_t smu[];
    const uint32_t sb = smem_u32(smu);
    const int tid = threadIdx.x, wid = tid >> 5, lane = tid & 31;
    const int g = lane >> 2, tg = lane & 3;
    const int bh = blockIdx.y, q0 = blockIdx.x * 128;
    const int qb = wid * 16;

    const float gam = fgamma[0], alpha = falpha[0];
    const bool g2 = (gam == 2.0f);

    const int r16 = lane & 15;
    const int sel = lane >> 4;
    const int rK  = (lane & 7) + ((lane >> 4) << 3);
    const int selB = (lane >> 3) & 1;

    auto cpQ = [&]() {
        int r = tid >> 1, hf = tid & 1;
        size_t src = ((size_t)bh * NSEQ + q0 + r) * 32 + hf * 16;
#pragma unroll
        for (int j = 0; j < 4; j++) {
            uint32_t d = (uint32_t)sw32(r, hf * 4 + j);
            cp16(sb + 4 * (FQH + d), g_Qh + src + 4 * j);
            cp16(sb + 4 * (FQL + d), g_Ql + src + 4 * j);
        }
    };
    auto cpKV = [&](int ch, int buf) {
        int r = tid >> 2, q4 = tid & 3;
        size_t src = ((size_t)bh * NSEQ + ch * 64 + r) * 32 + q4 * 8;
        uint32_t bo = FKV + (uint32_t)buf * FKVB;
#pragma unroll
        for (int j = 0; j < 2; j++) {
            uint32_t d = bo + (uint32_t)sw32(r, q4 * 2 + j);
            cp16(sb + 4 * d,           g_Kh + src + 4 * j);
            cp16(sb + 4 * (d + 2048),  g_Kl + src + 4 * j);
            cp16(sb + 4 * (d + 4096),  g_Vh + src + 4 * j);
            cp16(sb + 4 * (d + 6144),  g_Vl + src + 4 * j);
        }
    };

    cpQ(); cpKV(0, 0); CP_COMMIT();

    float o[8][4];
#pragma unroll
    for (int nt = 0; nt < 8; nt++) { o[nt][0] = o[nt][1] = o[nt][2] = o[nt][3] = 0.f; }
    float m0 = -1e30f, m1 = -1e30f, Z0 = 0.f, Z1 = 0.f, S20 = 0.f, S21 = 0.f;

    for (int ch = 0; ch < 32; ch++) {
        CP_WAIT0();
        __syncthreads();
        if (ch + 1 < 32) cpKV(ch + 1, (ch + 1) & 1);
        CP_COMMIT();

        const uint32_t kvb = FKV + (uint32_t)((ch & 1) * FKVB);

        // ---- S = Q K^T ----
        float s[8][4];
#pragma unroll
        for (int nt = 0; nt < 8; nt++) { s[nt][0] = s[nt][1] = s[nt][2] = s[nt][3] = 0.f; }
#pragma unroll
        for (int ks = 0; ks < 4; ks++) {
            const int cA = 2 * ks + sel;
            const int cB = 2 * ks + selB;
            uint32_t qh[4], ql[4];
            ldmx4(qh, sb + 4u * (uint32_t)(FQH + sw32(qb + r16, cA)));
            ldmx4(ql, sb + 4u * (uint32_t)(FQL + sw32(qb + r16, cA)));
#pragma unroll
            for (int np = 0; np < 2; np++) {
                const int n0 = np * 2;
                uint32_t th0[4], th1[4], tl0[4], tl1[4];
                ldmx4(th0, sb + 4u * (uint32_t)(kvb + sw32(rK + n0 * 16, cB)));
                ldmx4(th1, sb + 4u * (uint32_t)(kvb + sw32(rK + (n0 + 1) * 16, cB)));
                ldmx4(tl0, sb + 4u * (uint32_t)(kvb + 2048 + sw32(rK + n0 * 16, cB)));
                ldmx4(tl1, sb + 4u * (uint32_t)(kvb + 2048 + sw32(rK + (n0 + 1) * 16, cB)));
                mma16(s[2*n0],   qh, &th0[0]); mma16(s[2*n0+1], qh, &th0[2]);
                mma16(s[2*n0+2], qh, &th1[0]); mma16(s[2*n0+3], qh, &th1[2]);
                mma16(s[2*n0],   qh, &tl0[0]); mma16(s[2*n0+1], qh, &tl0[2]);
                mma16(s[2*n0+2], qh, &tl1[0]); mma16(s[2*n0+3], qh, &tl1[2]);
                mma16(s[2*n0],   ql, &th0[0]); mma16(s[2*n0+1], ql, &th0[2]);
                mma16(s[2*n0+2], ql, &th1[0]); mma16(s[2*n0+3], ql, &th1[2]);
            }
        }

        // ---- chunk max per row (quad reduce) ----
        float cm0 = -1e30f, cm1 = -1e30f;
#pragma unroll
        for (int nt = 0; nt < 8; nt++) {
            cm0 = fmaxf(cm0, fmaxf(s[nt][0], s[nt][1]));
            cm1 = fmaxf(cm1, fmaxf(s[nt][2], s[nt][3]));
        }
        cm0 = fmaxf(cm0, __shfl_xor_sync(0xffffffffu, cm0, 1));
        cm0 = fmaxf(cm0, __shfl_xor_sync(0xffffffffu, cm0, 2));
        cm1 = fmaxf(cm1, __shfl_xor_sync(0xffffffffu, cm1, 1));
        cm1 = fmaxf(cm1, __shfl_xor_sync(0xffffffffu, cm1, 2));

        // ---- online rescale ----
        float nm0 = fmaxf(m0, cm0), nm1 = fmaxf(m1, cm1);
        float cz0 = __expf(m0 - nm0), cz1 = __expf(m1 - nm1);
        float cw0 = g2 ? cz0 * cz0 : __expf(gam * (m0 - nm0));
        float cw1 = g2 ? cz1 * cz1 : __expf(gam * (m1 - nm1));
        Z0 *= cz0; Z1 *= cz1; S20 *= cw0; S21 *= cw1; m0 = nm0; m1 = nm1;
#pragma unroll
        for (int nt = 0; nt < 8; nt++) {
            o[nt][0] *= cw0; o[nt][1] *= cw0; o[nt][2] *= cw1; o[nt][3] *= cw1;
        }

        // ---- weights -> register A-frags for PV (C-frag layout == A-frag) ----
        uint32_t ph[4][4], pl[4][4];
        float zp0 = 0.f, zp1 = 0.f, wp0 = 0.f, wp1 = 0.f;
#pragma unroll
        for (int nt = 0; nt < 8; nt++) {
            float e0 = __expf(s[nt][0] - m0), e1 = __expf(s[nt][1] - m0);
            float e2 = __expf(s[nt][2] - m1), e3 = __expf(s[nt][3] - m1);
            zp0 += e0 + e1; zp1 += e2 + e3;
            float w0, w1, w2, w3;
            if (g2) { w0 = e0 * e0; w1 = e1 * e1; w2 = e2 * e2; w3 = e3 * e3; }
            else {
                w0 = __expf(gam * (s[nt][0] - m0)); w1 = __expf(gam * (s[nt][1] - m0));
                w2 = __expf(gam * (s[nt][2] - m1)); w3 = __expf(gam * (s[nt][3] - m1));
            }
            wp0 += w0 + w1; wp1 += w2 + w3;
            const int ks = nt >> 1, off = (nt & 1) * 2;
            ph[ks][off]     = packhi2(w0, w1);
            ph[ks][off + 1] = packhi2(w2, w3);
            pl[ks][off]     = packlo2(w0, w1);
            pl[ks][off + 1] = packlo2(w2, w3);
        }
        Z0 += zp0; Z1 += zp1; S20 += wp0; S21 += wp1;

        // ---- O += P V (P from registers) ----
#pragma unroll
        for (int ks = 0; ks < 4; ks++) {
            const int k0 = ks * 16;
#pragma unroll
            for (int dp2 = 0; dp2 < 2; dp2++) {
                const int d0 = dp2 * 2;
                uint32_t th0[4], th1[4], tl0[4], tl1[4];
                ldmx4t(th0, sb + 4u * (uint32_t)(kvb + 4096 + sw32(k0 + r16, d0 * 2 + sel)));
                ldmx4t(th1, sb + 4u * (uint32_t)(kvb + 4096 + sw32(k0 + r16, (d0 + 1) * 2 + sel)));
                ldmx4t(tl0, sb + 4u * (uint32_t)(kvb + 6144 + sw32(k0 + r16, d0 * 2 + sel)));
                ldmx4t(tl1, sb + 4u * (uint32_t)(kvb + 6144 + sw32(k0 + r16, (d0 + 1) * 2 + sel)));
                mma16(o[2*d0],   ph[ks], &th0[0]); mma16(o[2*d0+1], ph[ks], &th0[2]);
                mma16(o[2*d0+2], ph[ks], &th1[0]); mma16(o[2*d0+3], ph[ks], &th1[2]);
                mma16(o[2*d0],   ph[ks], &tl0[0]); mma16(o[2*d0+1], ph[ks], &tl0[2]);
                mma16(o[2*d0+2], ph[ks], &tl1[0]); mma16(o[2*d0+3], ph[ks], &tl1[2]);
                mma16(o[2*d0],   pl[ks], &th0[0]); mma16(o[2*d0+1], pl[ks], &th0[2]);
                mma16(o[2*d0+2], pl[ks], &th1[0]); mma16(o[2*d0+3], pl[ks], &th1[2]);
            }
        }
    }

    // ---- final reduce + packed split write of AO ----
    Z0  += __shfl_xor_sync(0xffffffffu, Z0, 1);  Z0  += __shfl_xor_sync(0xffffffffu, Z0, 2);
    Z1  += __shfl_xor_sync(0xffffffffu, Z1, 1);  Z1  += __shfl_xor_sync(0xffffffffu, Z1, 2);
    S20 += __shfl_xor_sync(0xffffffffu, S20, 1); S20 += __shfl_xor_sync(0xffffffffu, S20, 2);
    S21 += __shfl_xor_sync(0xffffffffu, S21, 1); S21 += __shfl_xor_sync(0xffffffffu, S21, 2);

    float Zg0 = g2 ? Z0 * Z0 : __powf(Z0, gam);
    float Zg1 = g2 ? Z1 * Z1 : __powf(Z1, gam);
    float sc0 = alpha / (alpha * S20 + 1e-6f * Zg0);
    float sc1 = alpha / (alpha * S21 + 1e-6f * Zg1);

    const int b = bh >> 4, h = bh & 15;
    const int qA = q0 + qb + g, qB = qA + 8;
#pragma unroll
    for (int nt = 0; nt < 8; nt++) {
        int d = nt * 8 + 2 * tg;
        size_t wA = ((size_t)b * NSEQ + qA) * 512 + ((h * HD_ + d) >> 1);
        size_t wB = ((size_t)b * NSEQ + qB) * 512 + ((h * HD_ + d) >> 1);
        float a0 = o[nt][0] * sc0, a1 = o[nt][1] * sc0;
        float b0 = o[nt][2] * sc1, b1 = o[nt][3] * sc1;
        g_AOh[wA] = packhi2(a0, a1); g_AOl[wA] = packlo2(a0, a1);
        g_AOh[wB] = packhi2(b0, b1); g_AOl[wB] = packlo2(b0, b1);
    }
}

// ---------------------------------------------------------------------------
extern "C" void kernel_launch(void* const* d_in, const int* in_sizes, int n_in,
                              void* d_out, int out_size)
{
    const float* x = nullptr, *Wqkv = nullptr, *bqkv = nullptr;
    const float* Wproj = nullptr, *bproj = nullptr, *fa = nullptr, *fg = nullptr;
    for (int i = 0; i < n_in; i++) {
        int sz = in_sizes[i];
        const float* p = (const float*)d_in[i];
        if      (sz == B_*NSEQ*DIM_)   x = p;
        else if (sz == 3*DIM_*DIM_)    Wqkv = p;
        else if (sz == 3*DIM_)         bqkv = p;
        else if (sz == DIM_*DIM_)      Wproj = p;
        else if (sz == DIM_)           bproj = p;
        else if (sz == 1)              { if (!fa) fa = p; else fg = p; }
    }
    float* out = (float*)d_out;

    cudaFuncSetAttribute(tc_gemm<0>,   cudaFuncAttributeMaxDynamicSharedMemorySize, GEMM_SMEM);
    cudaFuncSetAttribute(tc_gemm<1>,   cudaFuncAttributeMaxDynamicSharedMemorySize, GEMM_SMEM);
    cudaFuncSetAttribute(flash_kernel, cudaFuncAttributeMaxDynamicSharedMemorySize, FLASH_SMEM);

    // 0) Split inputs into packed bf16 hi/lo
    split_kernel<<<4096, 256>>>((const float4*)x,     0, 4096*256);
    split_kernel<<<3072, 256>>>((const float4*)Wqkv,  1, 3072*256);
    split_kernel<<<1024, 256>>>((const float4*)Wproj, 2, 1024*256);
    // 1) Fused QKV projection -> packed Q(scaled)/K/V
    tc_gemm<0><<<dim3(3*DIM_/128, (B_*NSEQ)/128), 256, GEMM_SMEM>>>(bqkv, nullptr);
    // 2) Focal flash attention -> packed AO
    flash_kernel<<<dim3(NSEQ/128, B_*H_), 256, FLASH_SMEM>>>(fa, fg);
    // 3) Output projection -> d_out
    tc_gemm<1><<<dim3(DIM_/128, (B_*NSEQ)/128), 256, GEMM_SMEM>>>(bproj, out);
}